// round 1
// baseline (speedup 1.0000x reference)
#include <cuda_runtime.h>
#include <math.h>

// ---------------- problem constants ----------------
#define BB 128
#define TT 8
#define LL 8
#define HID 64

// conv shapes
// conv1: in (128,3,192,256)  w(32,3,5,5)  s2 -> (128,32,94,126)
// conv2: in (128,32,94,126)  w(64,32,3,3) s2 -> (128,64,46,62)
// conv3: in (128,64,46,62)   w(64,64,3,3) s2 -> (128,64,22,30)
#define C1_CIN 3
#define C1_K 5
#define C1_HI 192
#define C1_WI 256
#define C1_HO 94
#define C1_WO 126
#define C1_CO 32

#define C2_CIN 32
#define C2_K 3
#define C2_HI 94
#define C2_WI 126
#define C2_HO 46
#define C2_WO 62
#define C2_CO 64

#define C3_CIN 64
#define C3_K 3
#define C3_HI 46
#define C3_WI 62
#define C3_HO 22
#define C3_WO 30
#define C3_CO 64

#define FC1_K 42240   // 64*22*30
#define FC1_N 256

// ---------------- scratch (device globals, no allocs) ----------------
__device__ float g_c1[(size_t)BB * C1_CO * C1_HO * C1_WO];   // 48.5M floats
__device__ float g_c2[(size_t)BB * C2_CO * C2_HO * C2_WO];   // 23.4M floats
__device__ float g_c3[(size_t)BB * C3_CO * C3_HO * C3_WO];   // 5.4M floats
__device__ float g_fc1[BB * FC1_N];
__device__ float g_cnn1[BB * 128];
__device__ float g_cnn2[BB * 128];
__device__ float g_act1[BB * TT * 16];
__device__ float g_a[BB * TT * 16];
__device__ float g_h[LL * TT * BB * HID];
__device__ float g_cst[LL * TT * BB * HID];
__device__ float g_lstm_out[BB * TT * HID];
__device__ float g_out1[BB * TT * 32];
__device__ float g_mo[BB * TT * 4];

// ---------------- direct conv, stride 2, 4co x 4wo microtile ----------------
template <int CIN, int KS>
__global__ void conv_s2_kernel(const float* __restrict__ in,
                               const float* __restrict__ wt,
                               const float* __restrict__ bs,
                               float* __restrict__ out,
                               int N, int Cout, int Hi, int Wi, int Ho, int Wo,
                               int relu)
{
    const int WO4 = (Wo + 3) >> 2;
    const int CO4 = Cout >> 2;
    long gid = (long)blockIdx.x * blockDim.x + threadIdx.x;
    long total = (long)N * CO4 * Ho * WO4;
    if (gid >= total) return;

    int wo4 = (int)(gid % WO4); long tmp = gid / WO4;
    int ho  = (int)(tmp % Ho);  tmp /= Ho;
    int co4 = (int)(tmp % CO4);
    int n   = (int)(tmp / CO4);
    int co0 = co4 * 4;
    int wo0 = wo4 * 4;

    float acc[4][4];
    #pragma unroll
    for (int c = 0; c < 4; c++) {
        float bv = bs[co0 + c];
        #pragma unroll
        for (int j = 0; j < 4; j++) acc[c][j] = bv;
    }

    constexpr int WIN  = KS + 6;        // input cols needed for 4 outputs
    constexpr int NV2  = (WIN + 1) / 2; // float2 loads
    const bool fast = (wo0 + 4 <= Wo);  // all 4 outputs valid -> vector path in-bounds

    const int wstride = CIN * KS * KS;  // per-co weight stride

    #pragma unroll 1
    for (int ci = 0; ci < CIN; ci++) {
        const float* wci = wt + (co0 * wstride) + ci * KS * KS;
        #pragma unroll
        for (int kh = 0; kh < KS; kh++) {
            const float* irow = in + (((long)(n * CIN + ci) * Hi) + (ho * 2 + kh)) * Wi + wo0 * 2;
            float vals[NV2 * 2];
            if (fast) {
                const float2* p = reinterpret_cast<const float2*>(irow);
                #pragma unroll
                for (int v = 0; v < NV2; v++) {
                    float2 t2 = p[v];
                    vals[2 * v] = t2.x; vals[2 * v + 1] = t2.y;
                }
            } else {
                #pragma unroll
                for (int v = 0; v < NV2 * 2; v++) {
                    int col = wo0 * 2 + v;
                    vals[v] = (col < Wi) ? irow[v] : 0.0f;
                }
            }
            #pragma unroll
            for (int kw = 0; kw < KS; kw++) {
                float w0 = wci[0 * wstride + kh * KS + kw];
                float w1 = wci[1 * wstride + kh * KS + kw];
                float w2 = wci[2 * wstride + kh * KS + kw];
                float w3 = wci[3 * wstride + kh * KS + kw];
                #pragma unroll
                for (int j = 0; j < 4; j++) {
                    float iv = vals[2 * j + kw];
                    acc[0][j] += iv * w0;
                    acc[1][j] += iv * w1;
                    acc[2][j] += iv * w2;
                    acc[3][j] += iv * w3;
                }
            }
        }
    }

    #pragma unroll
    for (int c = 0; c < 4; c++) {
        #pragma unroll
        for (int j = 0; j < 4; j++) {
            int wo = wo0 + j;
            if (wo < Wo) {
                float v = acc[c][j];
                if (relu) v = fmaxf(v, 0.0f);
                out[(((long)(n * Cout + co0 + c)) * Ho + ho) * Wo + wo] = v;
            }
        }
    }
}

// ---------------- fc1: split-K tiled GEMM, C(128,256) = A(128,42240) @ B(256,42240)^T ----------------
// grid (N/64=4, M/64=2, 33), 256 threads, K chunk = 1280 = 80 * BK(16)
__global__ void fc1_init_kernel(const float* __restrict__ b, float* __restrict__ C)
{
    int idx = blockIdx.x * blockDim.x + threadIdx.x;
    if (idx < BB * FC1_N) C[idx] = b[idx % FC1_N];
}

__global__ void fc1_gemm_kernel(const float* __restrict__ A,
                                const float* __restrict__ B,
                                float* __restrict__ C)
{
    __shared__ float As[16][68];
    __shared__ float Bs[16][68];

    const int tid = threadIdx.x;
    const int m0 = blockIdx.y * 64;
    const int n0 = blockIdx.x * 64;
    const int k0 = blockIdx.z * 1280;

    const int lr = tid >> 2;        // 0..63
    const int lc = (tid & 3) * 4;   // 0,4,8,12

    const float* Ap = A + (long)(m0 + lr) * FC1_K + k0 + lc;
    const float* Bp = B + (long)(n0 + lr) * FC1_K + k0 + lc;

    const int ty = tid >> 4, tx = tid & 15;
    float acc[4][4] = {};

    for (int it = 0; it < 80; it++) {
        float4 av = *reinterpret_cast<const float4*>(Ap + it * 16);
        float4 bv = *reinterpret_cast<const float4*>(Bp + it * 16);
        __syncthreads();
        As[lc + 0][lr] = av.x; As[lc + 1][lr] = av.y; As[lc + 2][lr] = av.z; As[lc + 3][lr] = av.w;
        Bs[lc + 0][lr] = bv.x; Bs[lc + 1][lr] = bv.y; Bs[lc + 2][lr] = bv.z; Bs[lc + 3][lr] = bv.w;
        __syncthreads();
        #pragma unroll
        for (int kk = 0; kk < 16; kk++) {
            float a[4], b[4];
            #pragma unroll
            for (int i = 0; i < 4; i++) a[i] = As[kk][ty * 4 + i];
            #pragma unroll
            for (int j = 0; j < 4; j++) b[j] = Bs[kk][tx * 4 + j];
            #pragma unroll
            for (int i = 0; i < 4; i++)
                #pragma unroll
                for (int j = 0; j < 4; j++)
                    acc[i][j] += a[i] * b[j];
        }
    }

    #pragma unroll
    for (int i = 0; i < 4; i++)
        #pragma unroll
        for (int j = 0; j < 4; j++)
            atomicAdd(&C[(m0 + ty * 4 + i) * FC1_N + (n0 + tx * 4 + j)], acc[i][j]);
}

// ---------------- generic small linear: out(M,N) = [relu?](in)(M,K) @ w(N,K)^T + b ----------------
__global__ void lin_kernel(const float* __restrict__ in,
                           const float* __restrict__ w,
                           const float* __restrict__ bias,
                           float* __restrict__ out,
                           int M, int N, int K, int reluIn)
{
    int idx = blockIdx.x * blockDim.x + threadIdx.x;
    if (idx >= M * N) return;
    int n = idx % N, m = idx / N;
    const float* ip = in + (long)m * K;
    const float* wp = w + (long)n * K;
    float acc = bias[n];
    if (reluIn) {
        for (int k = 0; k < K; k++) acc += fmaxf(ip[k], 0.0f) * wp[k];
    } else {
        for (int k = 0; k < K; k++) acc += ip[k] * wp[k];
    }
    out[idx] = acc;
}

// ---------------- LSTM wavefront: all cells (l,t) with l+t==wave in one launch ----------------
__device__ __forceinline__ float sigf(float x) { return 1.0f / (1.0f + expf(-x)); }

__global__ void lstm_wave_kernel(int wave,
                                 const float* __restrict__ a,        // (B*T,16)
                                 const float* __restrict__ cnn2,     // (B,128): [:,0:64]=c0, [:,64:128]=h0
                                 const float* __restrict__ Wih0,     // (256,16)
                                 const float* __restrict__ Wih,      // (7,256,64)
                                 const float* __restrict__ Whh,      // (8,256,64)
                                 const float* __restrict__ bih,      // (8,256)
                                 const float* __restrict__ bhh,      // (8,256)
                                 float* __restrict__ h_arr,          // (L,T,B,64)
                                 float* __restrict__ c_arr,
                                 float* __restrict__ lstm_out)       // (B,T,64)
{
    int l_lo = wave - (TT - 1); if (l_lo < 0) l_lo = 0;
    int l_hi = wave; if (l_hi > LL - 1) l_hi = LL - 1;
    int ncells = l_hi - l_lo + 1;

    long gid = (long)blockIdx.x * blockDim.x + threadIdx.x;
    int cell = (int)(gid / (BB * HID));
    if (cell >= ncells) return;
    int r = (int)(gid % (BB * HID));
    int b = r / HID, j = r % HID;
    int l = l_lo + cell;
    int t = wave - l;

    const float* x;
    const float* WihL;
    int in_dim;
    if (l == 0) { x = a + (b * TT + t) * 16; in_dim = 16; WihL = Wih0; }
    else        { x = h_arr + (((long)((l - 1) * TT + t) * BB) + b) * HID; in_dim = HID; WihL = Wih + (long)(l - 1) * 256 * HID; }

    const float* h_prev = (t == 0) ? (cnn2 + b * 128 + HID)
                                   : (h_arr + (((long)(l * TT + (t - 1)) * BB) + b) * HID);
    float c_prev = (t == 0) ? cnn2[b * 128 + j]
                            : c_arr[(((long)(l * TT + (t - 1)) * BB) + b) * HID + j];

    float g4[4];
    #pragma unroll
    for (int q = 0; q < 4; q++) g4[q] = bih[l * 256 + q * HID + j] + bhh[l * 256 + q * HID + j];

    for (int k = 0; k < in_dim; k++) {
        float xv = x[k];
        #pragma unroll
        for (int q = 0; q < 4; q++) g4[q] += xv * WihL[(q * HID + j) * in_dim + k];
    }
    const float* WhhL = Whh + (long)l * 256 * HID;
    for (int k = 0; k < HID; k++) {
        float hv = h_prev[k];
        #pragma unroll
        for (int q = 0; q < 4; q++) g4[q] += hv * WhhL[(q * HID + j) * HID + k];
    }

    float i_ = sigf(g4[0]);
    float f_ = sigf(g4[1]);
    float gg = tanhf(g4[2]);
    float o_ = sigf(g4[3]);
    float c  = f_ * c_prev + i_ * gg;
    float h  = o_ * tanhf(c);

    long pos = (((long)(l * TT + t) * BB) + b) * HID + j;
    h_arr[pos] = h;
    c_arr[pos] = c;
    if (l == LL - 1) lstm_out[(b * TT + t) * HID + j] = h;
}

// ---------------- finalize: rotation + translate + concat ----------------
__global__ void finalize_kernel(const float* __restrict__ mo,  // (B*T,4)
                                const float* __restrict__ gt,  // (B,T,6)
                                float* __restrict__ out)       // (B,T,4)
{
    int idx = blockIdx.x * blockDim.x + threadIdx.x;
    if (idx >= BB * TT) return;
    int b = idx / TT;
    float yaw = gt[b * (TT * 6) + 5];      // gt[b,0,5]
    float cy = cosf(yaw), sy = sinf(yaw);
    float m0 = mo[idx * 4 + 0];
    float m1 = mo[idx * 4 + 1];
    float m2 = mo[idx * 4 + 2];
    float m3 = mo[idx * 4 + 3];
    float tx = gt[b * (TT * 6) + 1];
    float ty = gt[b * (TT * 6) + 2];
    float tz = gt[b * (TT * 6) + 3];
    out[idx * 4 + 0] =  m0 * cy + m1 * sy + tx;
    out[idx * 4 + 1] = -m0 * sy + m1 * cy + ty;
    out[idx * 4 + 2] =  m2 + tz;
    out[idx * 4 + 3] =  m3;
}

// ---------------- launch ----------------
extern "C" void kernel_launch(void* const* d_in, const int* in_sizes, int n_in,
                              void* d_out, int out_size)
{
    const float* image    = (const float*)d_in[0];
    const float* act_in   = (const float*)d_in[1];
    const float* gt       = (const float*)d_in[2];
    const float* conv1_w  = (const float*)d_in[3];
    const float* conv1_b  = (const float*)d_in[4];
    const float* conv2_w  = (const float*)d_in[5];
    const float* conv2_b  = (const float*)d_in[6];
    const float* conv3_w  = (const float*)d_in[7];
    const float* conv3_b  = (const float*)d_in[8];
    const float* fc1_w    = (const float*)d_in[9];
    const float* fc1_b    = (const float*)d_in[10];
    const float* fc2_w    = (const float*)d_in[11];
    const float* fc2_b    = (const float*)d_in[12];
    const float* lowd1_w  = (const float*)d_in[13];
    const float* lowd1_b  = (const float*)d_in[14];
    const float* lowd2_w  = (const float*)d_in[15];
    const float* lowd2_b  = (const float*)d_in[16];
    const float* act1_w   = (const float*)d_in[17];
    const float* act1_b   = (const float*)d_in[18];
    const float* act2_w   = (const float*)d_in[19];
    const float* act2_b   = (const float*)d_in[20];
    const float* Wih0     = (const float*)d_in[21];
    const float* Wih      = (const float*)d_in[22];
    const float* Whh      = (const float*)d_in[23];
    const float* bih      = (const float*)d_in[24];
    const float* bhh      = (const float*)d_in[25];
    const float* out1_w   = (const float*)d_in[26];
    const float* out1_b   = (const float*)d_in[27];
    const float* out2_w   = (const float*)d_in[28];
    const float* out2_b   = (const float*)d_in[29];
    float* out = (float*)d_out;

    float *c1, *c2, *c3, *fc1o, *cnn1, *cnn2, *a1, *a2, *hA, *cA, *lo, *o1, *mo;
    cudaGetSymbolAddress((void**)&c1,   g_c1);
    cudaGetSymbolAddress((void**)&c2,   g_c2);
    cudaGetSymbolAddress((void**)&c3,   g_c3);
    cudaGetSymbolAddress((void**)&fc1o, g_fc1);
    cudaGetSymbolAddress((void**)&cnn1, g_cnn1);
    cudaGetSymbolAddress((void**)&cnn2, g_cnn2);
    cudaGetSymbolAddress((void**)&a1,   g_act1);
    cudaGetSymbolAddress((void**)&a2,   g_a);
    cudaGetSymbolAddress((void**)&hA,   g_h);
    cudaGetSymbolAddress((void**)&cA,   g_cst);
    cudaGetSymbolAddress((void**)&lo,   g_lstm_out);
    cudaGetSymbolAddress((void**)&o1,   g_out1);
    cudaGetSymbolAddress((void**)&mo,   g_mo);

    const int THR = 256;

    // conv1 (relu)
    {
        long total = (long)BB * (C1_CO / 4) * C1_HO * ((C1_WO + 3) / 4);
        conv_s2_kernel<C1_CIN, C1_K><<<(int)((total + THR - 1) / THR), THR>>>(
            image, conv1_w, conv1_b, c1, BB, C1_CO, C1_HI, C1_WI, C1_HO, C1_WO, 1);
    }
    // conv2 (relu)
    {
        long total = (long)BB * (C2_CO / 4) * C2_HO * ((C2_WO + 3) / 4);
        conv_s2_kernel<C2_CIN, C2_K><<<(int)((total + THR - 1) / THR), THR>>>(
            c1, conv2_w, conv2_b, c2, BB, C2_CO, C2_HI, C2_WI, C2_HO, C2_WO, 1);
    }
    // conv3 (no relu)
    {
        long total = (long)BB * (C3_CO / 4) * C3_HO * ((C3_WO + 3) / 4);
        conv_s2_kernel<C3_CIN, C3_K><<<(int)((total + THR - 1) / THR), THR>>>(
            c2, conv3_w, conv3_b, c3, BB, C3_CO, C3_HI, C3_WI, C3_HO, C3_WO, 0);
    }
    // fc1: init bias, split-K GEMM (atomic)
    fc1_init_kernel<<<(BB * FC1_N + THR - 1) / THR, THR>>>(fc1_b, fc1o);
    {
        dim3 grid(FC1_N / 64, BB / 64, 33);
        fc1_gemm_kernel<<<grid, 256>>>(c3, fc1_w, fc1o);
    }
    // fc2 (reads relu(fc1)), -> cnn_out1
    lin_kernel<<<(BB * 128 + THR - 1) / THR, THR>>>(fc1o, fc2_w, fc2_b, cnn1, BB, 128, 256, 1);
    // lowd1 -> raw ; lowd2 reads relu -> cnn_out2
    lin_kernel<<<(BB * 128 + THR - 1) / THR, THR>>>(cnn1, lowd1_w, lowd1_b, cnn2, BB, 128, 128, 0);
    // reuse cnn1 as lowd2 target? keep separate: cnn2 holds lowd1 out temporarily -> final in cnn2
    // (do it in two buffers to stay simple)
    lin_kernel<<<(BB * 128 + THR - 1) / THR, THR>>>(cnn2, lowd2_w, lowd2_b, cnn1, BB, 128, 128, 1);
    // NOTE: cnn1 now holds cnn_out2 (final low-d embedding)

    // action path: act1 raw, act2 reads relu -> a
    lin_kernel<<<(BB * TT * 16 + THR - 1) / THR, THR>>>(act_in, act1_w, act1_b, a1, BB * TT, 16, 2, 0);
    lin_kernel<<<(BB * TT * 16 + THR - 1) / THR, THR>>>(a1, act2_w, act2_b, a2, BB * TT, 16, 16, 1);

    // LSTM wavefront: 15 launches
    for (int w = 0; w < LL + TT - 1; w++) {
        int l_lo = w - (TT - 1); if (l_lo < 0) l_lo = 0;
        int l_hi = w; if (l_hi > LL - 1) l_hi = LL - 1;
        int ncells = l_hi - l_lo + 1;
        int blocks = ncells * (BB * HID / THR); // 32 blocks per cell
        lstm_wave_kernel<<<blocks, THR>>>(w, a2, cnn1, Wih0, Wih, Whh, bih, bhh, hA, cA, lo);
    }

    // heads: out1 raw, out2 reads relu -> mo
    lin_kernel<<<(BB * TT * 32 + THR - 1) / THR, THR>>>(lo, out1_w, out1_b, o1, BB * TT, 32, 64, 0);
    lin_kernel<<<(BB * TT * 4 + THR - 1) / THR, THR>>>(o1, out2_w, out2_b, mo, BB * TT, 4, 32, 1);

    // finalize
    finalize_kernel<<<(BB * TT + THR - 1) / THR, THR>>>(mo, gt, out);
}

// round 2
// speedup vs baseline: 1.2908x; 1.2908x over previous
#include <cuda_runtime.h>
#include <math.h>

// ---------------- problem constants ----------------
#define BB 128
#define TT 8
#define LL 8
#define HID 64

#define C1_CIN 3
#define C1_K 5
#define C1_HI 192
#define C1_WI 256
#define C1_HO 94
#define C1_WO 126
#define C1_CO 32

#define C2_CIN 32
#define C2_K 3
#define C2_HI 94
#define C2_WI 126
#define C2_HO 46
#define C2_WO 62
#define C2_CO 64

#define C3_CIN 64
#define C3_K 3
#define C3_HI 46
#define C3_WI 62
#define C3_HO 22
#define C3_WO 30
#define C3_CO 64

#define FC1_K 42240
#define FC1_N 256

// ---------------- scratch ----------------
__device__ float g_c1[(size_t)BB * C1_CO * C1_HO * C1_WO];
__device__ float g_c2[(size_t)BB * C2_CO * C2_HO * C2_WO];
__device__ float g_c3[(size_t)BB * C3_CO * C3_HO * C3_WO];
__device__ float g_fc1[BB * FC1_N];
__device__ float g_cnn1[BB * 128];
__device__ float g_cnn2[BB * 128];
__device__ float g_act1[BB * TT * 16];
__device__ float g_a[BB * TT * 16];
__device__ float g_h[LL * TT * BB * HID];
__device__ float g_cst[LL * TT * BB * HID];
__device__ float g_lstm_out[BB * TT * HID];
__device__ float g_out1[BB * TT * 32];
__device__ float g_mo[BB * TT * 4];

// ---------------- conv: smem weights, block shares co4 ----------------
template <int CIN, int KS>
__global__ void conv_s2_smem(const float* __restrict__ in,
                             const float* __restrict__ wt,
                             const float* __restrict__ bs,
                             float* __restrict__ out,
                             int N, int Cout, int Hi, int Wi, int Ho, int Wo,
                             int relu)
{
    constexpr int WSZ = CIN * KS * KS * 4;
    __shared__ float Wsm[WSZ];
    __shared__ float Bsm[4];

    const int co0 = blockIdx.y * 4;
    const int n   = blockIdx.z;
    const int wstride = CIN * KS * KS;

    for (int idx = threadIdx.x; idx < WSZ; idx += blockDim.x) {
        int c = idx & 3;
        int ckk = idx >> 2;
        Wsm[idx] = wt[(co0 + c) * wstride + ckk];
    }
    if (threadIdx.x < 4) Bsm[threadIdx.x] = bs[co0 + threadIdx.x];
    __syncthreads();

    const int WO4 = (Wo + 3) >> 2;
    int pix = blockIdx.x * blockDim.x + threadIdx.x;
    if (pix >= Ho * WO4) return;
    int ho  = pix / WO4;
    int wo0 = (pix % WO4) * 4;

    float acc[4][4];
    #pragma unroll
    for (int c = 0; c < 4; c++) {
        float bv = Bsm[c];
        #pragma unroll
        for (int j = 0; j < 4; j++) acc[c][j] = bv;
    }

    constexpr int WIN = KS + 6;
    constexpr int NV2 = (WIN + 1) / 2;
    const bool fast = (wo0 + 4 <= Wo);

    #pragma unroll 1
    for (int ci = 0; ci < CIN; ci++) {
        #pragma unroll
        for (int kh = 0; kh < KS; kh++) {
            const float* irow = in + (((long)(n * CIN + ci) * Hi) + (ho * 2 + kh)) * Wi + wo0 * 2;
            float vals[NV2 * 2];
            if (fast) {
                const float2* p = reinterpret_cast<const float2*>(irow);
                #pragma unroll
                for (int v = 0; v < NV2; v++) {
                    float2 t2 = p[v];
                    vals[2 * v] = t2.x; vals[2 * v + 1] = t2.y;
                }
            } else {
                #pragma unroll
                for (int v = 0; v < NV2 * 2; v++) {
                    int col = wo0 * 2 + v;
                    vals[v] = (col < Wi) ? irow[v] : 0.0f;
                }
            }
            #pragma unroll
            for (int kw = 0; kw < KS; kw++) {
                float4 wv = *reinterpret_cast<const float4*>(&Wsm[(ci * KS * KS + kh * KS + kw) * 4]);
                #pragma unroll
                for (int j = 0; j < 4; j++) {
                    float iv = vals[2 * j + kw];
                    acc[0][j] += iv * wv.x;
                    acc[1][j] += iv * wv.y;
                    acc[2][j] += iv * wv.z;
                    acc[3][j] += iv * wv.w;
                }
            }
        }
    }

    #pragma unroll
    for (int c = 0; c < 4; c++) {
        #pragma unroll
        for (int j = 0; j < 4; j++) {
            int wo = wo0 + j;
            if (wo < Wo) {
                float v = acc[c][j];
                if (relu) v = fmaxf(v, 0.0f);
                out[(((long)(n * Cout + co0 + c)) * Ho + ho) * Wo + wo] = v;
            }
        }
    }
}

// ---------------- fc1 ----------------
__global__ void fc1_init_kernel(const float* __restrict__ b, float* __restrict__ C)
{
    int idx = blockIdx.x * blockDim.x + threadIdx.x;
    if (idx < BB * FC1_N) C[idx] = b[idx % FC1_N];
}

__global__ void fc1_gemm_kernel(const float* __restrict__ A,
                                const float* __restrict__ B,
                                float* __restrict__ C)
{
    __shared__ float As[16][72];
    __shared__ float Bs[16][72];

    const int tid = threadIdx.x;
    const int m0 = blockIdx.y * 64;
    const int n0 = blockIdx.x * 64;
    const int k0 = blockIdx.z * 1280;

    const int lr = tid >> 2;
    const int lc = (tid & 3) * 4;

    const float* Ap = A + (long)(m0 + lr) * FC1_K + k0 + lc;
    const float* Bp = B + (long)(n0 + lr) * FC1_K + k0 + lc;

    const int ty = tid >> 4, tx = tid & 15;
    float acc[4][4] = {};

    for (int it = 0; it < 80; it++) {
        float4 av = *reinterpret_cast<const float4*>(Ap + it * 16);
        float4 bv = *reinterpret_cast<const float4*>(Bp + it * 16);
        __syncthreads();
        As[lc + 0][lr] = av.x; As[lc + 1][lr] = av.y; As[lc + 2][lr] = av.z; As[lc + 3][lr] = av.w;
        Bs[lc + 0][lr] = bv.x; Bs[lc + 1][lr] = bv.y; Bs[lc + 2][lr] = bv.z; Bs[lc + 3][lr] = bv.w;
        __syncthreads();
        #pragma unroll
        for (int kk = 0; kk < 16; kk++) {
            float4 a4 = *reinterpret_cast<const float4*>(&As[kk][ty * 4]);
            float4 b4 = *reinterpret_cast<const float4*>(&Bs[kk][tx * 4]);
            float a[4] = {a4.x, a4.y, a4.z, a4.w};
            float b[4] = {b4.x, b4.y, b4.z, b4.w};
            #pragma unroll
            for (int i = 0; i < 4; i++)
                #pragma unroll
                for (int j = 0; j < 4; j++)
                    acc[i][j] += a[i] * b[j];
        }
    }

    #pragma unroll
    for (int i = 0; i < 4; i++)
        #pragma unroll
        for (int j = 0; j < 4; j++)
            atomicAdd(&C[(m0 + ty * 4 + i) * FC1_N + (n0 + tx * 4 + j)], acc[i][j]);
}

// ---------------- small linear: out(M,N) = act(in)(M,K) @ w(N,K)^T + b ----------------
// block: 32 m (blockIdx.x) x 32 n (blockIdx.y); 256 threads: lane=m, warp=4n
__global__ void lin2_kernel(const float* __restrict__ in,
                            const float* __restrict__ w,
                            const float* __restrict__ bias,
                            float* __restrict__ out,
                            int M, int N, int K, int reluIn)
{
    __shared__ float Xs[256 * 33];   // [k][m] padded, K<=256

    const int tid = threadIdx.x;
    const int m0 = blockIdx.x * 32;
    const int n0 = blockIdx.y * 32;

    for (int idx = tid; idx < 32 * K; idx += 256) {
        int m_l = idx / K;
        int k = idx - m_l * K;
        float v = in[(long)(m0 + m_l) * K + k];
        if (reluIn) v = fmaxf(v, 0.0f);
        Xs[k * 33 + m_l] = v;
    }
    __syncthreads();

    const int lane = tid & 31;
    const int wg = tid >> 5;
    const int m = m0 + lane;

    float acc[4] = {0.f, 0.f, 0.f, 0.f};
    const int K4 = K & ~3;

    for (int k4 = 0; k4 < K4; k4 += 4) {
        float xv0 = Xs[(k4 + 0) * 33 + lane];
        float xv1 = Xs[(k4 + 1) * 33 + lane];
        float xv2 = Xs[(k4 + 2) * 33 + lane];
        float xv3 = Xs[(k4 + 3) * 33 + lane];
        #pragma unroll
        for (int ni = 0; ni < 4; ni++) {
            int nn = n0 + wg * 4 + ni;
            if (nn < N) {
                float4 wv = *reinterpret_cast<const float4*>(&w[(long)nn * K + k4]);
                acc[ni] += xv0 * wv.x + xv1 * wv.y + xv2 * wv.z + xv3 * wv.w;
            }
        }
    }
    for (int k = K4; k < K; k++) {
        float xv = Xs[k * 33 + lane];
        #pragma unroll
        for (int ni = 0; ni < 4; ni++) {
            int nn = n0 + wg * 4 + ni;
            if (nn < N) acc[ni] += xv * w[(long)nn * K + k];
        }
    }

    #pragma unroll
    for (int ni = 0; ni < 4; ni++) {
        int nn = n0 + wg * 4 + ni;
        if (nn < N) out[(long)m * N + nn] = acc[ni] + bias[nn];
    }
}

// ---------------- LSTM wave kernel v2 ----------------
__device__ __forceinline__ float sigf(float x) { return 1.0f / (1.0f + expf(-x)); }

// block: one cell (l,t) x 8 batch rows. 256 threads: j = tid&63, bq = tid>>6 (2 b each)
__global__ void lstm_wave2_kernel(int wave,
                                  const float* __restrict__ a,      // (B,T,16)
                                  const float* __restrict__ cnn2,   // (B,128): c0|h0
                                  const float* __restrict__ Wih0,   // (256,16)
                                  const float* __restrict__ Wih,    // (7,256,64)
                                  const float* __restrict__ Whh,    // (8,256,64)
                                  const float* __restrict__ bih,    // (8,256)
                                  const float* __restrict__ bhh,
                                  float* __restrict__ h_arr,        // (L,T,B,64)
                                  float* __restrict__ c_arr,
                                  float* __restrict__ lstm_out)     // (B,T,64)
{
    __shared__ float Ws[32 * 257];   // [k][row] row = q*64+j, padded
    __shared__ float Xs[32 * 9];     // [k][b_local] padded

    const int cell = blockIdx.x >> 4;
    const int bblk = blockIdx.x & 15;
    int l_lo = wave - (TT - 1); if (l_lo < 0) l_lo = 0;
    const int l = l_lo + cell;
    const int t = wave - l;

    const int tid = threadIdx.x;
    const int j = tid & 63;
    const int bq = tid >> 6;          // 0..3
    const int b0 = bblk * 8;          // block covers b0..b0+7

    float acc[4][2];
    #pragma unroll
    for (int q = 0; q < 4; q++) {
        float bb = bih[l * 256 + q * 64 + j] + bhh[l * 256 + q * 64 + j];
        acc[q][0] = bb; acc[q][1] = bb;
    }

    // two phases: (Wih, x) then (Whh, h_prev)
    #pragma unroll 1
    for (int ph = 0; ph < 2; ph++) {
        const float* W;
        const float* xbase;
        int K, xstr;
        if (ph == 0) {
            if (l == 0) { W = Wih0; K = 16; xbase = a + t * 16; xstr = TT * 16; }
            else        { W = Wih + (long)(l - 1) * 256 * 64; K = 64;
                          xbase = h_arr + ((long)((l - 1) * TT + t)) * BB * 64; xstr = 64; }
        } else {
            W = Whh + (long)l * 256 * 64; K = 64;
            if (t == 0) { xbase = cnn2 + HID; xstr = 128; }
            else        { xbase = h_arr + ((long)(l * TT + (t - 1))) * BB * 64; xstr = 64; }
        }

        for (int k0 = 0; k0 < K; k0 += 32) {
            int kc = (K - k0 < 32) ? (K - k0) : 32;
            __syncthreads();
            // stage weights: kc*256 elements, coalesced in k
            for (int idx = tid; idx < kc * 256; idx += 256) {
                int r = idx / kc;
                int k = idx - r * kc;
                Ws[k * 257 + r] = W[(long)r * K + k0 + k];
            }
            // stage x: kc*8
            for (int idx = tid; idx < kc * 8; idx += 256) {
                int b_l = idx / kc;
                int k = idx - b_l * kc;
                Xs[k * 9 + b_l] = xbase[(long)(b0 + b_l) * xstr + k0 + k];
            }
            __syncthreads();
            #pragma unroll 8
            for (int k = 0; k < kc; k++) {
                float xv0 = Xs[k * 9 + (bq << 1)];
                float xv1 = Xs[k * 9 + (bq << 1) + 1];
                float w0 = Ws[k * 257 + j];
                float w1 = Ws[k * 257 + 64 + j];
                float w2 = Ws[k * 257 + 128 + j];
                float w3 = Ws[k * 257 + 192 + j];
                acc[0][0] += w0 * xv0; acc[0][1] += w0 * xv1;
                acc[1][0] += w1 * xv0; acc[1][1] += w1 * xv1;
                acc[2][0] += w2 * xv0; acc[2][1] += w2 * xv1;
                acc[3][0] += w3 * xv0; acc[3][1] += w3 * xv1;
            }
        }
    }

    #pragma unroll
    for (int i = 0; i < 2; i++) {
        int b = b0 + (bq << 1) + i;
        float c_prev = (t == 0) ? cnn2[b * 128 + j]
                                : c_arr[((long)(l * TT + (t - 1)) * BB + b) * 64 + j];
        float i_ = sigf(acc[0][i]);
        float f_ = sigf(acc[1][i]);
        float gg = tanhf(acc[2][i]);
        float o_ = sigf(acc[3][i]);
        float c  = f_ * c_prev + i_ * gg;
        float h  = o_ * tanhf(c);
        long pos = ((long)(l * TT + t) * BB + b) * 64 + j;
        h_arr[pos] = h;
        c_arr[pos] = c;
        if (l == LL - 1) lstm_out[(b * TT + t) * 64 + j] = h;
    }
}

// ---------------- finalize ----------------
__global__ void finalize_kernel(const float* __restrict__ mo,
                                const float* __restrict__ gt,
                                float* __restrict__ out)
{
    int idx = blockIdx.x * blockDim.x + threadIdx.x;
    if (idx >= BB * TT) return;
    int b = idx / TT;
    float yaw = gt[b * (TT * 6) + 5];
    float cy = cosf(yaw), sy = sinf(yaw);
    float m0 = mo[idx * 4 + 0];
    float m1 = mo[idx * 4 + 1];
    float m2 = mo[idx * 4 + 2];
    float m3 = mo[idx * 4 + 3];
    float tx = gt[b * (TT * 6) + 1];
    float ty = gt[b * (TT * 6) + 2];
    float tz = gt[b * (TT * 6) + 3];
    out[idx * 4 + 0] =  m0 * cy + m1 * sy + tx;
    out[idx * 4 + 1] = -m0 * sy + m1 * cy + ty;
    out[idx * 4 + 2] =  m2 + tz;
    out[idx * 4 + 3] =  m3;
}

// ---------------- launch ----------------
extern "C" void kernel_launch(void* const* d_in, const int* in_sizes, int n_in,
                              void* d_out, int out_size)
{
    const float* image    = (const float*)d_in[0];
    const float* act_in   = (const float*)d_in[1];
    const float* gt       = (const float*)d_in[2];
    const float* conv1_w  = (const float*)d_in[3];
    const float* conv1_b  = (const float*)d_in[4];
    const float* conv2_w  = (const float*)d_in[5];
    const float* conv2_b  = (const float*)d_in[6];
    const float* conv3_w  = (const float*)d_in[7];
    const float* conv3_b  = (const float*)d_in[8];
    const float* fc1_w    = (const float*)d_in[9];
    const float* fc1_b    = (const float*)d_in[10];
    const float* fc2_w    = (const float*)d_in[11];
    const float* fc2_b    = (const float*)d_in[12];
    const float* lowd1_w  = (const float*)d_in[13];
    const float* lowd1_b  = (const float*)d_in[14];
    const float* lowd2_w  = (const float*)d_in[15];
    const float* lowd2_b  = (const float*)d_in[16];
    const float* act1_w   = (const float*)d_in[17];
    const float* act1_b   = (const float*)d_in[18];
    const float* act2_w   = (const float*)d_in[19];
    const float* act2_b   = (const float*)d_in[20];
    const float* Wih0     = (const float*)d_in[21];
    const float* Wih      = (const float*)d_in[22];
    const float* Whh      = (const float*)d_in[23];
    const float* bih      = (const float*)d_in[24];
    const float* bhh      = (const float*)d_in[25];
    const float* out1_w   = (const float*)d_in[26];
    const float* out1_b   = (const float*)d_in[27];
    const float* out2_w   = (const float*)d_in[28];
    const float* out2_b   = (const float*)d_in[29];
    float* out = (float*)d_out;

    float *c1, *c2, *c3, *fc1o, *cnn1, *cnn2, *a1, *a2, *hA, *cA, *lo, *o1, *mo;
    cudaGetSymbolAddress((void**)&c1,   g_c1);
    cudaGetSymbolAddress((void**)&c2,   g_c2);
    cudaGetSymbolAddress((void**)&c3,   g_c3);
    cudaGetSymbolAddress((void**)&fc1o, g_fc1);
    cudaGetSymbolAddress((void**)&cnn1, g_cnn1);
    cudaGetSymbolAddress((void**)&cnn2, g_cnn2);
    cudaGetSymbolAddress((void**)&a1,   g_act1);
    cudaGetSymbolAddress((void**)&a2,   g_a);
    cudaGetSymbolAddress((void**)&hA,   g_h);
    cudaGetSymbolAddress((void**)&cA,   g_cst);
    cudaGetSymbolAddress((void**)&lo,   g_lstm_out);
    cudaGetSymbolAddress((void**)&o1,   g_out1);
    cudaGetSymbolAddress((void**)&mo,   g_mo);

    // conv1 (relu): Ho*WO4 = 94*32 = 3008
    {
        dim3 grid((3008 + 255) / 256, C1_CO / 4, BB);
        conv_s2_smem<C1_CIN, C1_K><<<grid, 256>>>(
            image, conv1_w, conv1_b, c1, BB, C1_CO, C1_HI, C1_WI, C1_HO, C1_WO, 1);
    }
    // conv2 (relu): 46*16 = 736
    {
        dim3 grid((736 + 255) / 256, C2_CO / 4, BB);
        conv_s2_smem<C2_CIN, C2_K><<<grid, 256>>>(
            c1, conv2_w, conv2_b, c2, BB, C2_CO, C2_HI, C2_WI, C2_HO, C2_WO, 1);
    }
    // conv3 (no relu): 22*8 = 176
    {
        dim3 grid(1, C3_CO / 4, BB);
        conv_s2_smem<C3_CIN, C3_K><<<grid, 192>>>(
            c2, conv3_w, conv3_b, c3, BB, C3_CO, C3_HI, C3_WI, C3_HO, C3_WO, 0);
    }
    // fc1
    fc1_init_kernel<<<(BB * FC1_N + 255) / 256, 256>>>(fc1_b, fc1o);
    {
        dim3 grid(FC1_N / 64, BB / 64, 33);
        fc1_gemm_kernel<<<grid, 256>>>(c3, fc1_w, fc1o);
    }
    // fc2: relu(fc1) -> cnn1 (128x128, K=256)
    { dim3 g(BB / 32, 4); lin2_kernel<<<g, 256>>>(fc1o, fc2_w, fc2_b, cnn1, BB, 128, 256, 1); }
    // lowd1: cnn1 raw -> cnn2 (K=128)
    { dim3 g(BB / 32, 4); lin2_kernel<<<g, 256>>>(cnn1, lowd1_w, lowd1_b, cnn2, BB, 128, 128, 0); }
    // lowd2: relu(cnn2) -> cnn1 (final embedding)
    { dim3 g(BB / 32, 4); lin2_kernel<<<g, 256>>>(cnn2, lowd2_w, lowd2_b, cnn1, BB, 128, 128, 1); }
    // action path
    { dim3 g(BB * TT / 32, 1); lin2_kernel<<<g, 256>>>(act_in, act1_w, act1_b, a1, BB * TT, 16, 2, 0); }
    { dim3 g(BB * TT / 32, 1); lin2_kernel<<<g, 256>>>(a1, act2_w, act2_b, a2, BB * TT, 16, 16, 1); }

    // LSTM: 15 waves
    for (int w = 0; w < LL + TT - 1; w++) {
        int l_lo = w - (TT - 1); if (l_lo < 0) l_lo = 0;
        int l_hi = w; if (l_hi > LL - 1) l_hi = LL - 1;
        int ncells = l_hi - l_lo + 1;
        lstm_wave2_kernel<<<ncells * 16, 256>>>(w, a2, cnn1, Wih0, Wih, Whh, bih, bhh, hA, cA, lo);
    }

    // heads
    { dim3 g(BB * TT / 32, 1); lin2_kernel<<<g, 256>>>(lo, out1_w, out1_b, o1, BB * TT, 32, 64, 0); }
    { dim3 g(BB * TT / 32, 1); lin2_kernel<<<g, 256>>>(o1, out2_w, out2_b, mo, BB * TT, 4, 32, 1); }

    finalize_kernel<<<(BB * TT + 255) / 256, 256>>>(mo, gt, out);
}